// round 13
// baseline (speedup 1.0000x reference)
#include <cuda_runtime.h>
#include <cuda_fp16.h>

#define NN     5000
#define NE     160000
#define HID    64
#define BATCH  512
#define CAP    128            // ELL row capacity (Poisson(32); P(deg>128) ~ 1e-40)

// ---------------- scratch (device globals; zero-init at module load) ----------------
__device__ int      g_cnt[NN];              // degree / ELL slot counter; re-zeroed by k_final
__device__ __align__(16) int g_ell[NN * CAP];
__device__ __align__(16) float   g_h1 [NN * HID];    // fp32 h1 (own-feature GEMM term)
__device__ __align__(8)  __half2 g_h1h[NN * 32];     // fp16 mirror (gather traffic)
__device__ __align__(16) float g_mean[NN * HID];
__device__ __align__(16) float g_hp[5120 * HID];     // rows [5000,5120) stay zero forever
__device__ __align__(16) float g_tpT[HID * BATCH];   // transposed: [h][b]

union U64 { unsigned long long u; float2 f; };

__device__ __forceinline__ unsigned long long pack2(float a, float b) {
    unsigned long long r;
    asm("mov.b64 %0, {%1, %2};" : "=l"(r) : "f"(a), "f"(b));
    return r;
}

__device__ __forceinline__ void fma2(unsigned long long& acc,
                                     unsigned long long a, unsigned long long b) {
    asm("fma.rn.f32x2 %0, %1, %2, %0;" : "+l"(acc) : "l"(a), "l"(b));
}

// per-block edge dtype detection: OR of 256 odd u32 words of this block's slice.
__device__ __forceinline__ int block_detect_i32(const unsigned* __restrict__ w, int e0) {
    __shared__ unsigned s_or[8];
    __shared__ int s_i32;
    int tid = threadIdx.x;
    unsigned odd = w[2 * (e0 + tid) + 1];
    odd = __reduce_or_sync(0xffffffffu, odd);
    if ((tid & 31) == 0) s_or[tid >> 5] = odd;
    __syncthreads();
    if (tid == 0) {
        unsigned a = 0;
#pragma unroll
        for (int i = 0; i < 8; i++) a |= s_or[i];
        s_i32 = (a != 0);
    }
    __syncthreads();
    return s_i32;
}

// -------- task MLP, one warp per batch, shuffle-based --------
__device__ __forceinline__ void do_task(int b, int lane, const float* __restrict__ tf,
                                        const float* __restrict__ Wt1, const float* __restrict__ bt1,
                                        const float* __restrict__ Wt2, const float* __restrict__ bt2,
                                        const float* __restrict__ Wc1, const float* __restrict__ bc1) {
    float4 f = *(const float4*)(tf + (size_t)b * 4);
    int o0 = lane, o1 = lane + 32;
    float a0 = bt1[o0] + Wt1[o0*4]*f.x + Wt1[o0*4+1]*f.y + Wt1[o0*4+2]*f.z + Wt1[o0*4+3]*f.w;
    float a1 = bt1[o1] + Wt1[o1*4]*f.x + Wt1[o1*4+1]*f.y + Wt1[o1*4+2]*f.z + Wt1[o1*4+3]*f.w;
    a0 = fmaxf(a0, 0.f); a1 = fmaxf(a1, 0.f);

    float c0 = bt2[o0], c1 = bt2[o1];
#pragma unroll
    for (int h = 0; h < 32; h++) {
        float v = __shfl_sync(0xffffffffu, a0, h);
        c0 += Wt2[o0*64 + h] * v;
        c1 += Wt2[o1*64 + h] * v;
    }
#pragma unroll
    for (int h = 0; h < 32; h++) {
        float v = __shfl_sync(0xffffffffu, a1, h);
        c0 += Wt2[o0*64 + 32 + h] * v;
        c1 += Wt2[o1*64 + 32 + h] * v;
    }
    float d0 = bc1[o0], d1 = bc1[o1];
#pragma unroll
    for (int h = 0; h < 32; h++) {
        float v = __shfl_sync(0xffffffffu, c0, h);
        d0 += Wc1[o0*128 + 64 + h] * v;
        d1 += Wc1[o1*128 + 64 + h] * v;
    }
#pragma unroll
    for (int h = 0; h < 32; h++) {
        float v = __shfl_sync(0xffffffffu, c1, h);
        d0 += Wc1[o0*128 + 96 + h] * v;
        d1 += Wc1[o1*128 + 96 + h] * v;
    }
    g_tpT[o0 * BATCH + b] = d0;
    g_tpT[o1 * BATCH + b] = d1;
}

// ---------------- 1) edge pass: ELL fill + degree; + task MLP ----------------
__global__ void __launch_bounds__(256) k_edge(
        const void* __restrict__ ei, const float* __restrict__ tf,
        const float* __restrict__ Wt1, const float* __restrict__ bt1,
        const float* __restrict__ Wt2, const float* __restrict__ bt2,
        const float* __restrict__ Wc1, const float* __restrict__ bc1) {
    int bx = blockIdx.x;
    if (bx >= 625) {
        int b = (bx - 625) * 8 + (threadIdx.x >> 5);
        do_task(b, threadIdx.x & 31, tf, Wt1, bt1, Wt2, bt2, Wc1, bc1);
        return;
    }
    int e = bx * 256 + threadIdx.x;
    int i32 = block_detect_i32((const unsigned*)ei, bx * 256);
    int s, d;
    if (i32) { const int* p = (const int*)ei; s = p[e]; d = p[NE + e]; }
    else     { const long long* p = (const long long*)ei; s = (int)p[e]; d = (int)p[NE + e]; }
    int slot = atomicAdd(&g_cnt[d], 1);
    if (slot < CAP) g_ell[d * CAP + slot] = s;
}

// ---------------- 2) layer-1: warp per node, ELL gather of x, fused matvec ----------------
__global__ void __launch_bounds__(256) k_node1(
        const float* __restrict__ x,
        const float* __restrict__ Wl1, const float* __restrict__ bl1,
        const float* __restrict__ Wr1) {
    int n    = blockIdx.x * 8 + (threadIdx.x >> 5);
    int lane = threadIdx.x & 31;
    int deg  = min(g_cnt[n], CAP);
    const int* row = g_ell + n * CAP;
    float4 a = make_float4(0.f, 0.f, 0.f, 0.f);
    for (int e = lane; e < deg; e += 32) {
        float4 xv = __ldg((const float4*)(x + (size_t)row[e] * 4));
        a.x += xv.x; a.y += xv.y; a.z += xv.z; a.w += xv.w;
    }
#pragma unroll
    for (int off = 16; off; off >>= 1) {
        a.x += __shfl_xor_sync(0xffffffffu, a.x, off);
        a.y += __shfl_xor_sync(0xffffffffu, a.y, off);
        a.z += __shfl_xor_sync(0xffffffffu, a.z, off);
        a.w += __shfl_xor_sync(0xffffffffu, a.w, off);
    }
    float invd = 1.f / fmaxf((float)deg, 1.f);
    float m0 = a.x*invd, m1 = a.y*invd, m2 = a.z*invd, m3 = a.w*invd;
    float4 xn = __ldg((const float4*)(x + (size_t)n * 4));
    int oa = 2 * lane, ob = 2 * lane + 1;
    float va = bl1[oa]
             + Wl1[oa*4]*m0 + Wl1[oa*4+1]*m1 + Wl1[oa*4+2]*m2 + Wl1[oa*4+3]*m3
             + Wr1[oa*4]*xn.x + Wr1[oa*4+1]*xn.y + Wr1[oa*4+2]*xn.z + Wr1[oa*4+3]*xn.w;
    float vb = bl1[ob]
             + Wl1[ob*4]*m0 + Wl1[ob*4+1]*m1 + Wl1[ob*4+2]*m2 + Wl1[ob*4+3]*m3
             + Wr1[ob*4]*xn.x + Wr1[ob*4+1]*xn.y + Wr1[ob*4+2]*xn.z + Wr1[ob*4+3]*xn.w;
    va = fmaxf(va, 0.f); vb = fmaxf(vb, 0.f);
    *(float2*)(g_h1 + (size_t)n * 64 + oa) = make_float2(va, vb);
    g_h1h[n * 32 + lane] = __floats2half2_rn(va, vb);
}

// ---------------- 3) mean gather over fp16 h1: warp per node, int4 edges, 4 chains ----------------
__global__ void __launch_bounds__(256) k_gather2() {
    int n    = blockIdx.x * 8 + (threadIdx.x >> 5);
    int lane = threadIdx.x & 31;
    int deg  = min(g_cnt[n], CAP);
    const int4* row = (const int4*)(g_ell + n * CAP);
    float2 a = make_float2(0.f, 0.f), b = make_float2(0.f, 0.f);
    float2 c = make_float2(0.f, 0.f), d = make_float2(0.f, 0.f);
    int nq = deg >> 2;
    for (int q = 0; q < nq; q++) {
        int4 s4 = row[q];
        float2 va = __half22float2(__ldg(&g_h1h[s4.x * 32 + lane]));
        float2 vb = __half22float2(__ldg(&g_h1h[s4.y * 32 + lane]));
        float2 vc = __half22float2(__ldg(&g_h1h[s4.z * 32 + lane]));
        float2 vd = __half22float2(__ldg(&g_h1h[s4.w * 32 + lane]));
        a.x += va.x; a.y += va.y;
        b.x += vb.x; b.y += vb.y;
        c.x += vc.x; c.y += vc.y;
        d.x += vd.x; d.y += vd.y;
    }
    for (int e = nq * 4; e < deg; e++) {
        int s = g_ell[n * CAP + e];
        float2 v = __half22float2(__ldg(&g_h1h[s * 32 + lane]));
        a.x += v.x; a.y += v.y;
    }
    float invd = 1.f / fmaxf((float)deg, 1.f);
    float2 m;
    m.x = (a.x + b.x + c.x + d.x) * invd;
    m.y = (a.y + b.y + c.y + d.y) * invd;
    *(float2*)(g_mean + (size_t)n * 64 + 2 * lane) = m;
}

// ---------------- 4) f32x2 GEMM: 1 node x 4 outs per thread (PROFILED) ----------------
// 512 threads = 16 out-groups x 32 nodes, grid 157, smem ~69KB -> 1 block/SM, 16 warps.
// Inner k: 4 LDS + 2 mov + 4 fma.f32x2 = 10 instr per 16 scalar FMA.
#define MM_NODES 32
#define MM_GRID  ((NN + MM_NODES - 1) / MM_NODES)    // 157
#define WS4 68                                       // float4-aligned weight stride
#define MS4 33                                       // feature stride (conflict-free)
#define SM_BYTES ((3*64*WS4 + 2*64*MS4) * 4)         // 69120 B
__global__ void __launch_bounds__(512) k_l2mm(const float* __restrict__ Wl2,
                                              const float* __restrict__ bl2,
                                              const float* __restrict__ Wr2,
                                              const float* __restrict__ Wc1) {
    extern __shared__ float sm[];
    float* sWl   = sm;                   // [k*WS4 + o]
    float* sWr   = sm + 64*WS4;
    float* sWc   = sm + 2*64*WS4;
    float* sMean = sm + 3*64*WS4;        // [k*MS4 + nl]; aliased as sH2 later
    float* sX    = sMean + 64*MS4;
    int tid = threadIdx.x;
    int n0 = blockIdx.x * MM_NODES;

    for (int idx = tid; idx < 4096; idx += 512) {
        int o = idx >> 6, k = idx & 63;          // coalesced global reads
        sWl[k*WS4 + o] = Wl2[idx];
        sWr[k*WS4 + o] = Wr2[idx];
        sWc[k*WS4 + o] = Wc1[o*128 + k];         // h-part of Wc1
    }
    for (int idx = tid; idx < 2048; idx += 512) {
        int nl = idx >> 6, k = idx & 63;
        int n = n0 + nl;
        bool ok = (n < NN);
        sMean[k*MS4 + nl] = ok ? g_mean[n*64 + k] : 0.f;
        sX[k*MS4 + nl]    = ok ? g_h1[n*64 + k]   : 0.f;
    }
    __syncthreads();

    int tx = tid & 15, nl = tid >> 4;    // tx: out group (4 outs), nl: node 0..31
    int o0 = tx * 4;

    // packed accumulators: acc01 = outs (o0,o0+1), acc23 = (o0+2,o0+3)
    ulonglong2 bb = *(const ulonglong2*)(bl2 + o0);
    U64 acc01, acc23;
    acc01.u = bb.x; acc23.u = bb.y;
#pragma unroll
    for (int k = 0; k < 64; k++) {
        float m  = sMean[k*MS4 + nl];
        float xv = sX[k*MS4 + nl];
        ulonglong2 wl = *(const ulonglong2*)(sWl + k*WS4 + o0);
        ulonglong2 wr = *(const ulonglong2*)(sWr + k*WS4 + o0);
        unsigned long long mm = pack2(m, m);
        unsigned long long xx = pack2(xv, xv);
        fma2(acc01.u, mm, wl.x);
        fma2(acc23.u, mm, wl.y);
        fma2(acc01.u, xx, wr.x);
        fma2(acc23.u, xx, wr.y);
    }
    acc01.f.x = fmaxf(acc01.f.x, 0.f); acc01.f.y = fmaxf(acc01.f.y, 0.f);
    acc23.f.x = fmaxf(acc23.f.x, 0.f); acc23.f.y = fmaxf(acc23.f.y, 0.f);
    __syncthreads();                     // all sMean/sX reads complete

    float* sH2 = sMean;                  // alias: [o*MS4 + nl]
    sH2[(o0+0)*MS4 + nl] = acc01.f.x;
    sH2[(o0+1)*MS4 + nl] = acc01.f.y;
    sH2[(o0+2)*MS4 + nl] = acc23.f.x;
    sH2[(o0+3)*MS4 + nl] = acc23.f.y;
    __syncthreads();

    U64 p01, p23;
    p01.u = 0ull; p23.u = 0ull;
#pragma unroll
    for (int k = 0; k < 64; k++) {
        float h2 = sH2[k*MS4 + nl];
        ulonglong2 wc = *(const ulonglong2*)(sWc + k*WS4 + o0);
        unsigned long long hh = pack2(h2, h2);
        fma2(p01.u, hh, wc.x);
        fma2(p23.u, hh, wc.y);
    }
    int n = n0 + nl;
    if (n < NN)
        *(float4*)(g_hp + (size_t)n * 64 + o0) =
            make_float4(p01.f.x, p01.f.y, p23.f.x, p23.f.y);
}

// ---------------- 5) final scores + re-zero side job ----------------
// Tile 128 nodes x 64 batches, 256 threads, grid (40,8).
#define FIN_SMEM (64*129*4 + 64*64*4 + 64*8)
__global__ void __launch_bounds__(256) k_final(const float* __restrict__ Wc2,
                                               const float* __restrict__ bc2,
                                               float* __restrict__ out) {
    extern __shared__ float smf[];
    float* s_hp = smf;                         // [h][r], stride 129
    float* s_tp = smf + 64 * 129;              // [h][b], 64 wide
    unsigned long long* s_w2 = (unsigned long long*)(smf + 64 * 129 + 64 * 64);
    int tid = threadIdx.x;

    // side job: re-zero degree counters (blocks 0..19 x 256 = 5120 >= 5000)
    int bid = blockIdx.y * gridDim.x + blockIdx.x;
    if (bid < 20) {
        int i = bid * 256 + tid;
        if (i < NN) g_cnt[i] = 0;
    }

    int n0 = blockIdx.x * 128, b0 = blockIdx.y * 64;
    for (int idx = tid; idx < 8192; idx += 256) {
        int r = idx >> 6, h = idx & 63;
        s_hp[h*129 + r] = g_hp[(size_t)(n0 + r) * 64 + h];
    }
    for (int idx = tid; idx < 4096; idx += 256) {
        int h = idx >> 6, b = idx & 63;
        s_tp[h*64 + b] = g_tpT[h * BATCH + b0 + b];
    }
    if (tid < 64) { float w = Wc2[tid]; s_w2[tid] = pack2(w, w); }
    __syncthreads();

    int nla = tid & 63, q = tid >> 6;          // q in {0..3}: 16 batches each
    int nlb = nla + 64;
    U64 accA[8], accB[8];
#pragma unroll
    for (int p = 0; p < 8; p++) { accA[p].u = 0ull; accB[p].u = 0ull; }

#pragma unroll 4
    for (int h = 0; h < 64; h++) {
        float hva = s_hp[h*129 + nla];
        float hvb = s_hp[h*129 + nlb];
        unsigned long long ha = pack2(hva, hva);
        unsigned long long hb = pack2(hvb, hvb);
        unsigned long long w2 = s_w2[h];
        const unsigned long long* tp = (const unsigned long long*)(s_tp + h*64 + q*16);
#pragma unroll
        for (int p = 0; p < 8; p++) {
            unsigned long long t2 = tp[p];
            U64 a, b;
            asm("add.rn.f32x2 %0, %1, %2;" : "=l"(a.u) : "l"(t2), "l"(ha));
            asm("add.rn.f32x2 %0, %1, %2;" : "=l"(b.u) : "l"(t2), "l"(hb));
            a.f.x = fmaxf(a.f.x, 0.f); a.f.y = fmaxf(a.f.y, 0.f);
            b.f.x = fmaxf(b.f.x, 0.f); b.f.y = fmaxf(b.f.y, 0.f);
            asm("fma.rn.f32x2 %0, %1, %2, %0;" : "+l"(accA[p].u) : "l"(a.u), "l"(w2));
            asm("fma.rn.f32x2 %0, %1, %2, %0;" : "+l"(accB[p].u) : "l"(b.u), "l"(w2));
        }
    }

    float bias = bc2[0];
    int na = n0 + nla, nb = n0 + nlb;
    if (na < NN) {
#pragma unroll
        for (int p = 0; p < 8; p++) {
            int b = b0 + q*16 + 2*p;
            out[(size_t)b       * NN + na] = accA[p].f.x + bias;
            out[(size_t)(b + 1) * NN + na] = accA[p].f.y + bias;
        }
    }
    if (nb < NN) {
#pragma unroll
        for (int p = 0; p < 8; p++) {
            int b = b0 + q*16 + 2*p;
            out[(size_t)b       * NN + nb] = accB[p].f.x + bias;
            out[(size_t)(b + 1) * NN + nb] = accB[p].f.y + bias;
        }
    }
}

// ---------------- launch ----------------
extern "C" void kernel_launch(void* const* d_in, const int* in_sizes, int n_in,
                              void* d_out, int out_size) {
    const float* x   = (const float*)d_in[0];
    const void*  ei  = d_in[1];
    const float* tf  = (const float*)d_in[2];
    const float* Wl1 = (const float*)d_in[3];
    const float* bl1 = (const float*)d_in[4];
    const float* Wr1 = (const float*)d_in[5];
    const float* Wl2 = (const float*)d_in[6];
    const float* bl2 = (const float*)d_in[7];
    const float* Wr2 = (const float*)d_in[8];
    const float* Wt1 = (const float*)d_in[9];
    const float* bt1 = (const float*)d_in[10];
    const float* Wt2 = (const float*)d_in[11];
    const float* bt2 = (const float*)d_in[12];
    const float* Wc1 = (const float*)d_in[13];
    const float* bc1 = (const float*)d_in[14];
    const float* Wc2 = (const float*)d_in[15];
    const float* bc2 = (const float*)d_in[16];
    float* out = (float*)d_out;

    static bool attr_set = false;
    if (!attr_set) {
        cudaFuncSetAttribute(k_l2mm,  cudaFuncAttributeMaxDynamicSharedMemorySize, SM_BYTES);
        cudaFuncSetAttribute(k_final, cudaFuncAttributeMaxDynamicSharedMemorySize, FIN_SMEM);
        attr_set = true;
    }

    k_edge   <<<689, 256>>>(ei, tf, Wt1, bt1, Wt2, bt2, Wc1, bc1);
    k_node1  <<<625, 256>>>(x, Wl1, bl1, Wr1);
    k_gather2<<<625, 256>>>();
    k_l2mm   <<<MM_GRID, 512, SM_BYTES>>>(Wl2, bl2, Wr2, Wc1);   // 4th -> profiled
    k_final  <<<dim3(40, 8), 256, FIN_SMEM>>>(Wc2, bc2, out);
}

// round 14
// speedup vs baseline: 1.0129x; 1.0129x over previous
#include <cuda_runtime.h>
#include <cuda_fp16.h>

#define NN     5000
#define NE     160000
#define HID    64
#define BATCH  512
#define CAP    128            // ELL row capacity (Poisson(32); P(deg>128) ~ 1e-40)

// ---------------- scratch (device globals; zero-init at module load) ----------------
__device__ int      g_cnt[NN];              // degree / ELL slot counter; re-zeroed by k_final
__device__ __align__(16) int g_ell[NN * CAP];
__device__ __align__(16) float   g_h1 [NN * HID];    // fp32 h1 (own-feature GEMM term)
__device__ __align__(8)  __half2 g_h1h[NN * 32];     // fp16 mirror (gather traffic)
__device__ __align__(16) float g_mean[NN * HID];
__device__ __align__(16) float g_hp[5120 * HID];     // rows [5000,5120) stay zero forever
__device__ __align__(16) float g_tpT[HID * BATCH];   // transposed: [h][b]
__device__ __align__(16) float g_WlT[HID * HID];     // Wl2 transposed [k][o]
__device__ __align__(16) float g_WrT[HID * HID];     // Wr2 transposed [k][o]
__device__ __align__(16) float g_WcT[HID * HID];     // Wc1 h-part transposed [k][o]

union U64 { unsigned long long u; float2 f; };

__device__ __forceinline__ unsigned long long pack2(float a, float b) {
    unsigned long long r;
    asm("mov.b64 %0, {%1, %2};" : "=l"(r) : "f"(a), "f"(b));
    return r;
}

// per-block edge dtype detection: OR of 256 odd u32 words of this block's slice.
__device__ __forceinline__ int block_detect_i32(const unsigned* __restrict__ w, int e0) {
    __shared__ unsigned s_or[8];
    __shared__ int s_i32;
    int tid = threadIdx.x;
    unsigned odd = w[2 * (e0 + tid) + 1];
    odd = __reduce_or_sync(0xffffffffu, odd);
    if ((tid & 31) == 0) s_or[tid >> 5] = odd;
    __syncthreads();
    if (tid == 0) {
        unsigned a = 0;
#pragma unroll
        for (int i = 0; i < 8; i++) a |= s_or[i];
        s_i32 = (a != 0);
    }
    __syncthreads();
    return s_i32;
}

// -------- task MLP, one warp per batch, shuffle-based --------
__device__ __forceinline__ void do_task(int b, int lane, const float* __restrict__ tf,
                                        const float* __restrict__ Wt1, const float* __restrict__ bt1,
                                        const float* __restrict__ Wt2, const float* __restrict__ bt2,
                                        const float* __restrict__ Wc1, const float* __restrict__ bc1) {
    float4 f = *(const float4*)(tf + (size_t)b * 4);
    int o0 = lane, o1 = lane + 32;
    float a0 = bt1[o0] + Wt1[o0*4]*f.x + Wt1[o0*4+1]*f.y + Wt1[o0*4+2]*f.z + Wt1[o0*4+3]*f.w;
    float a1 = bt1[o1] + Wt1[o1*4]*f.x + Wt1[o1*4+1]*f.y + Wt1[o1*4+2]*f.z + Wt1[o1*4+3]*f.w;
    a0 = fmaxf(a0, 0.f); a1 = fmaxf(a1, 0.f);

    float c0 = bt2[o0], c1 = bt2[o1];
#pragma unroll
    for (int h = 0; h < 32; h++) {
        float v = __shfl_sync(0xffffffffu, a0, h);
        c0 += Wt2[o0*64 + h] * v;
        c1 += Wt2[o1*64 + h] * v;
    }
#pragma unroll
    for (int h = 0; h < 32; h++) {
        float v = __shfl_sync(0xffffffffu, a1, h);
        c0 += Wt2[o0*64 + 32 + h] * v;
        c1 += Wt2[o1*64 + 32 + h] * v;
    }
    float d0 = bc1[o0], d1 = bc1[o1];
#pragma unroll
    for (int h = 0; h < 32; h++) {
        float v = __shfl_sync(0xffffffffu, c0, h);
        d0 += Wc1[o0*128 + 64 + h] * v;
        d1 += Wc1[o1*128 + 64 + h] * v;
    }
#pragma unroll
    for (int h = 0; h < 32; h++) {
        float v = __shfl_sync(0xffffffffu, c1, h);
        d0 += Wc1[o0*128 + 96 + h] * v;
        d1 += Wc1[o1*128 + 96 + h] * v;
    }
    g_tpT[o0 * BATCH + b] = d0;
    g_tpT[o1 * BATCH + b] = d1;
}

// ---------------- 1) edge pass: ELL fill + degree; + task MLP; + weight transposes ----------------
__global__ void __launch_bounds__(256) k_edge(
        const void* __restrict__ ei, const float* __restrict__ tf,
        const float* __restrict__ Wt1, const float* __restrict__ bt1,
        const float* __restrict__ Wt2, const float* __restrict__ bt2,
        const float* __restrict__ Wc1, const float* __restrict__ bc1,
        const float* __restrict__ Wl2, const float* __restrict__ Wr2) {
    int bx = blockIdx.x;
    if (bx >= 689) {
        // transpose blocks: 48 blocks x 256 = 12288 = 3 x 4096
        int idx = (bx - 689) * 256 + threadIdx.x;
        int arr = idx >> 12, e = idx & 4095;
        int o = e >> 6, k = e & 63;
        if (arr == 0)      g_WlT[k*64 + o] = Wl2[o*64 + k];
        else if (arr == 1) g_WrT[k*64 + o] = Wr2[o*64 + k];
        else               g_WcT[k*64 + o] = Wc1[o*128 + k];   // h-part of Wc1
        return;
    }
    if (bx >= 625) {
        int b = (bx - 625) * 8 + (threadIdx.x >> 5);
        do_task(b, threadIdx.x & 31, tf, Wt1, bt1, Wt2, bt2, Wc1, bc1);
        return;
    }
    int e = bx * 256 + threadIdx.x;
    int i32 = block_detect_i32((const unsigned*)ei, bx * 256);
    int s, d;
    if (i32) { const int* p = (const int*)ei; s = p[e]; d = p[NE + e]; }
    else     { const long long* p = (const long long*)ei; s = (int)p[e]; d = (int)p[NE + e]; }
    int slot = atomicAdd(&g_cnt[d], 1);
    if (slot < CAP) g_ell[d * CAP + slot] = s;
}

// ---------------- 2) layer-1: warp per node, ELL gather of x, fused matvec ----------------
__global__ void __launch_bounds__(256) k_node1(
        const float* __restrict__ x,
        const float* __restrict__ Wl1, const float* __restrict__ bl1,
        const float* __restrict__ Wr1) {
    int n    = blockIdx.x * 8 + (threadIdx.x >> 5);
    int lane = threadIdx.x & 31;
    int deg  = min(g_cnt[n], CAP);
    const int* row = g_ell + n * CAP;
    float4 a = make_float4(0.f, 0.f, 0.f, 0.f);
    for (int e = lane; e < deg; e += 32) {
        float4 xv = __ldg((const float4*)(x + (size_t)row[e] * 4));
        a.x += xv.x; a.y += xv.y; a.z += xv.z; a.w += xv.w;
    }
#pragma unroll
    for (int off = 16; off; off >>= 1) {
        a.x += __shfl_xor_sync(0xffffffffu, a.x, off);
        a.y += __shfl_xor_sync(0xffffffffu, a.y, off);
        a.z += __shfl_xor_sync(0xffffffffu, a.z, off);
        a.w += __shfl_xor_sync(0xffffffffu, a.w, off);
    }
    float invd = 1.f / fmaxf((float)deg, 1.f);
    float m0 = a.x*invd, m1 = a.y*invd, m2 = a.z*invd, m3 = a.w*invd;
    float4 xn = __ldg((const float4*)(x + (size_t)n * 4));
    int oa = 2 * lane, ob = 2 * lane + 1;
    float va = bl1[oa]
             + Wl1[oa*4]*m0 + Wl1[oa*4+1]*m1 + Wl1[oa*4+2]*m2 + Wl1[oa*4+3]*m3
             + Wr1[oa*4]*xn.x + Wr1[oa*4+1]*xn.y + Wr1[oa*4+2]*xn.z + Wr1[oa*4+3]*xn.w;
    float vb = bl1[ob]
             + Wl1[ob*4]*m0 + Wl1[ob*4+1]*m1 + Wl1[ob*4+2]*m2 + Wl1[ob*4+3]*m3
             + Wr1[ob*4]*xn.x + Wr1[ob*4+1]*xn.y + Wr1[ob*4+2]*xn.z + Wr1[ob*4+3]*xn.w;
    va = fmaxf(va, 0.f); vb = fmaxf(vb, 0.f);
    *(float2*)(g_h1 + (size_t)n * 64 + oa) = make_float2(va, vb);
    g_h1h[n * 32 + lane] = __floats2half2_rn(va, vb);
}

// ---------------- 3) mean gather over fp16 h1: warp per node, int4 edges, 4 chains ----------------
__global__ void __launch_bounds__(256) k_gather2() {
    int n    = blockIdx.x * 8 + (threadIdx.x >> 5);
    int lane = threadIdx.x & 31;
    int deg  = min(g_cnt[n], CAP);
    const int4* row = (const int4*)(g_ell + n * CAP);
    float2 a = make_float2(0.f, 0.f), b = make_float2(0.f, 0.f);
    float2 c = make_float2(0.f, 0.f), d = make_float2(0.f, 0.f);
    int nq = deg >> 2;
    for (int q = 0; q < nq; q++) {
        int4 s4 = row[q];
        float2 va = __half22float2(__ldg(&g_h1h[s4.x * 32 + lane]));
        float2 vb = __half22float2(__ldg(&g_h1h[s4.y * 32 + lane]));
        float2 vc = __half22float2(__ldg(&g_h1h[s4.z * 32 + lane]));
        float2 vd = __half22float2(__ldg(&g_h1h[s4.w * 32 + lane]));
        a.x += va.x; a.y += va.y;
        b.x += vb.x; b.y += vb.y;
        c.x += vc.x; c.y += vc.y;
        d.x += vd.x; d.y += vd.y;
    }
    for (int e = nq * 4; e < deg; e++) {
        int s = g_ell[n * CAP + e];
        float2 v = __half22float2(__ldg(&g_h1h[s * 32 + lane]));
        a.x += v.x; a.y += v.y;
    }
    float invd = 1.f / fmaxf((float)deg, 1.f);
    float2 m;
    m.x = (a.x + b.x + c.x + d.x) * invd;
    m.y = (a.y + b.y + c.y + d.y) * invd;
    *(float2*)(g_mean + (size_t)n * 64 + 2 * lane) = m;
}

// ---------------- 4) l2 GEMM: warp per node, shuffle-broadcast feats, L1-resident WT ----------------
// grid 625 x 256 (8 warps = 8 nodes/block). Lane L owns outs 2L, 2L+1.
__global__ void __launch_bounds__(256) k_l2sh(const float* __restrict__ bl2) {
    int n    = blockIdx.x * 8 + (threadIdx.x >> 5);
    int lane = threadIdx.x & 31;
    int o0   = 2 * lane;

    float2 md = *(const float2*)(g_mean + (size_t)n * 64 + o0);  // feats o0,o0+1
    float2 xd = *(const float2*)(g_h1   + (size_t)n * 64 + o0);
    float2 acc = *(const float2*)(bl2 + o0);

#pragma unroll
    for (int kk = 0; kk < 32; kk++) {
        float mx = __shfl_sync(0xffffffffu, md.x, kk);
        float my = __shfl_sync(0xffffffffu, md.y, kk);
        float xx = __shfl_sync(0xffffffffu, xd.x, kk);
        float xy = __shfl_sync(0xffffffffu, xd.y, kk);
        int k0 = 2 * kk;
        float2 wl0 = __ldg((const float2*)(g_WlT + k0*64 + o0));
        float2 wr0 = __ldg((const float2*)(g_WrT + k0*64 + o0));
        float2 wl1 = __ldg((const float2*)(g_WlT + (k0+1)*64 + o0));
        float2 wr1 = __ldg((const float2*)(g_WrT + (k0+1)*64 + o0));
        acc.x += mx*wl0.x + xx*wr0.x + my*wl1.x + xy*wr1.x;
        acc.y += mx*wl0.y + xx*wr0.y + my*wl1.y + xy*wr1.y;
    }
    float2 h2 = make_float2(fmaxf(acc.x, 0.f), fmaxf(acc.y, 0.f));

    float2 p = make_float2(0.f, 0.f);
#pragma unroll
    for (int kk = 0; kk < 32; kk++) {
        float hx = __shfl_sync(0xffffffffu, h2.x, kk);
        float hy = __shfl_sync(0xffffffffu, h2.y, kk);
        int k0 = 2 * kk;
        float2 wc0 = __ldg((const float2*)(g_WcT + k0*64 + o0));
        float2 wc1 = __ldg((const float2*)(g_WcT + (k0+1)*64 + o0));
        p.x += hx*wc0.x + hy*wc1.x;
        p.y += hx*wc0.y + hy*wc1.y;
    }
    *(float2*)(g_hp + (size_t)n * 64 + o0) = p;
}

// ---------------- 5) final scores + re-zero side job ----------------
// Tile 128 nodes x 64 batches, 256 threads, grid (40,8).
#define FIN_SMEM (64*129*4 + 64*64*4 + 64*8)
__global__ void __launch_bounds__(256) k_final(const float* __restrict__ Wc2,
                                               const float* __restrict__ bc2,
                                               float* __restrict__ out) {
    extern __shared__ float smf[];
    float* s_hp = smf;                         // [h][r], stride 129
    float* s_tp = smf + 64 * 129;              // [h][b], 64 wide
    unsigned long long* s_w2 = (unsigned long long*)(smf + 64 * 129 + 64 * 64);
    int tid = threadIdx.x;

    // side job: re-zero degree counters (blocks 0..19 x 256 = 5120 >= 5000)
    int bid = blockIdx.y * gridDim.x + blockIdx.x;
    if (bid < 20) {
        int i = bid * 256 + tid;
        if (i < NN) g_cnt[i] = 0;
    }

    int n0 = blockIdx.x * 128, b0 = blockIdx.y * 64;
    for (int idx = tid; idx < 8192; idx += 256) {
        int r = idx >> 6, h = idx & 63;
        s_hp[h*129 + r] = g_hp[(size_t)(n0 + r) * 64 + h];
    }
    for (int idx = tid; idx < 4096; idx += 256) {
        int h = idx >> 6, b = idx & 63;
        s_tp[h*64 + b] = g_tpT[h * BATCH + b0 + b];
    }
    if (tid < 64) { float w = Wc2[tid]; s_w2[tid] = pack2(w, w); }
    __syncthreads();

    int nla = tid & 63, q = tid >> 6;          // q in {0..3}: 16 batches each
    int nlb = nla + 64;
    U64 accA[8], accB[8];
#pragma unroll
    for (int p = 0; p < 8; p++) { accA[p].u = 0ull; accB[p].u = 0ull; }

#pragma unroll 4
    for (int h = 0; h < 64; h++) {
        float hva = s_hp[h*129 + nla];
        float hvb = s_hp[h*129 + nlb];
        unsigned long long ha = pack2(hva, hva);
        unsigned long long hb = pack2(hvb, hvb);
        unsigned long long w2 = s_w2[h];
        const unsigned long long* tp = (const unsigned long long*)(s_tp + h*64 + q*16);
#pragma unroll
        for (int p = 0; p < 8; p++) {
            unsigned long long t2 = tp[p];
            U64 a, b;
            asm("add.rn.f32x2 %0, %1, %2;" : "=l"(a.u) : "l"(t2), "l"(ha));
            asm("add.rn.f32x2 %0, %1, %2;" : "=l"(b.u) : "l"(t2), "l"(hb));
            a.f.x = fmaxf(a.f.x, 0.f); a.f.y = fmaxf(a.f.y, 0.f);
            b.f.x = fmaxf(b.f.x, 0.f); b.f.y = fmaxf(b.f.y, 0.f);
            asm("fma.rn.f32x2 %0, %1, %2, %0;" : "+l"(accA[p].u) : "l"(a.u), "l"(w2));
            asm("fma.rn.f32x2 %0, %1, %2, %0;" : "+l"(accB[p].u) : "l"(b.u), "l"(w2));
        }
    }

    float bias = bc2[0];
    int na = n0 + nla, nb = n0 + nlb;
    if (na < NN) {
#pragma unroll
        for (int p = 0; p < 8; p++) {
            int b = b0 + q*16 + 2*p;
            out[(size_t)b       * NN + na] = accA[p].f.x + bias;
            out[(size_t)(b + 1) * NN + na] = accA[p].f.y + bias;
        }
    }
    if (nb < NN) {
#pragma unroll
        for (int p = 0; p < 8; p++) {
            int b = b0 + q*16 + 2*p;
            out[(size_t)b       * NN + nb] = accB[p].f.x + bias;
            out[(size_t)(b + 1) * NN + nb] = accB[p].f.y + bias;
        }
    }
}

// ---------------- launch ----------------
extern "C" void kernel_launch(void* const* d_in, const int* in_sizes, int n_in,
                              void* d_out, int out_size) {
    const float* x   = (const float*)d_in[0];
    const void*  ei  = d_in[1];
    const float* tf  = (const float*)d_in[2];
    const float* Wl1 = (const float*)d_in[3];
    const float* bl1 = (const float*)d_in[4];
    const float* Wr1 = (const float*)d_in[5];
    const float* Wl2 = (const float*)d_in[6];
    const float* bl2 = (const float*)d_in[7];
    const float* Wr2 = (const float*)d_in[8];
    const float* Wt1 = (const float*)d_in[9];
    const float* bt1 = (const float*)d_in[10];
    const float* Wt2 = (const float*)d_in[11];
    const float* bt2 = (const float*)d_in[12];
    const float* Wc1 = (const float*)d_in[13];
    const float* bc1 = (const float*)d_in[14];
    const float* Wc2 = (const float*)d_in[15];
    const float* bc2 = (const float*)d_in[16];
    float* out = (float*)d_out;

    static bool attr_set = false;
    if (!attr_set) {
        cudaFuncSetAttribute(k_final, cudaFuncAttributeMaxDynamicSharedMemorySize, FIN_SMEM);
        attr_set = true;
    }

    k_edge   <<<737, 256>>>(ei, tf, Wt1, bt1, Wt2, bt2, Wc1, bc1, Wl2, Wr2);
    k_node1  <<<625, 256>>>(x, Wl1, bl1, Wr1);
    k_gather2<<<625, 256>>>();
    k_l2sh   <<<625, 256>>>(bl2);                                  // 4th -> profiled
    k_final  <<<dim3(40, 8), 256, FIN_SMEM>>>(Wc2, bc2, out);
}

// round 15
// speedup vs baseline: 1.0548x; 1.0413x over previous
#include <cuda_runtime.h>
#include <cuda_fp16.h>

#define NN     5000
#define NE     160000
#define HID    64
#define BATCH  512
#define CAP    128            // ELL row capacity (Poisson(32); P(deg>128) ~ 1e-40)

// ---------------- scratch (device globals; zero-init at module load) ----------------
__device__ int      g_cnt[NN];              // degree / ELL slot counter; re-zeroed by k_final
__device__ __align__(16) int g_ell[NN * CAP];
__device__ __align__(16) float   g_h1 [NN * HID];    // fp32 h1 (own-feature GEMM term)
__device__ __align__(8)  __half2 g_h1h[NN * 32];     // fp16 mirror (gather traffic)
__device__ __align__(16) float g_mean[NN * HID];
__device__ __align__(16) float g_hp[5120 * HID];     // rows [5000,5120) stay zero forever
__device__ __align__(16) float g_tpT[HID * BATCH];   // transposed: [h][b]

union U64 { unsigned long long u; float2 f; };

__device__ __forceinline__ unsigned long long pack2(float a, float b) {
    unsigned long long r;
    asm("mov.b64 %0, {%1, %2};" : "=l"(r) : "f"(a), "f"(b));
    return r;
}

// per-block edge dtype detection: OR of 256 odd u32 words of this block's slice.
__device__ __forceinline__ int block_detect_i32(const unsigned* __restrict__ w, int e0) {
    __shared__ unsigned s_or[8];
    __shared__ int s_i32;
    int tid = threadIdx.x;
    unsigned odd = w[2 * (e0 + tid) + 1];
    odd = __reduce_or_sync(0xffffffffu, odd);
    if ((tid & 31) == 0) s_or[tid >> 5] = odd;
    __syncthreads();
    if (tid == 0) {
        unsigned a = 0;
#pragma unroll
        for (int i = 0; i < 8; i++) a |= s_or[i];
        s_i32 = (a != 0);
    }
    __syncthreads();
    return s_i32;
}

// -------- task MLP, one warp per batch, shuffle-based --------
__device__ __forceinline__ void do_task(int b, int lane, const float* __restrict__ tf,
                                        const float* __restrict__ Wt1, const float* __restrict__ bt1,
                                        const float* __restrict__ Wt2, const float* __restrict__ bt2,
                                        const float* __restrict__ Wc1, const float* __restrict__ bc1) {
    float4 f = *(const float4*)(tf + (size_t)b * 4);
    int o0 = lane, o1 = lane + 32;
    float a0 = bt1[o0] + Wt1[o0*4]*f.x + Wt1[o0*4+1]*f.y + Wt1[o0*4+2]*f.z + Wt1[o0*4+3]*f.w;
    float a1 = bt1[o1] + Wt1[o1*4]*f.x + Wt1[o1*4+1]*f.y + Wt1[o1*4+2]*f.z + Wt1[o1*4+3]*f.w;
    a0 = fmaxf(a0, 0.f); a1 = fmaxf(a1, 0.f);

    float c0 = bt2[o0], c1 = bt2[o1];
#pragma unroll
    for (int h = 0; h < 32; h++) {
        float v = __shfl_sync(0xffffffffu, a0, h);
        c0 += Wt2[o0*64 + h] * v;
        c1 += Wt2[o1*64 + h] * v;
    }
#pragma unroll
    for (int h = 0; h < 32; h++) {
        float v = __shfl_sync(0xffffffffu, a1, h);
        c0 += Wt2[o0*64 + 32 + h] * v;
        c1 += Wt2[o1*64 + 32 + h] * v;
    }
    float d0 = bc1[o0], d1 = bc1[o1];
#pragma unroll
    for (int h = 0; h < 32; h++) {
        float v = __shfl_sync(0xffffffffu, c0, h);
        d0 += Wc1[o0*128 + 64 + h] * v;
        d1 += Wc1[o1*128 + 64 + h] * v;
    }
#pragma unroll
    for (int h = 0; h < 32; h++) {
        float v = __shfl_sync(0xffffffffu, c1, h);
        d0 += Wc1[o0*128 + 96 + h] * v;
        d1 += Wc1[o1*128 + 96 + h] * v;
    }
    g_tpT[o0 * BATCH + b] = d0;
    g_tpT[o1 * BATCH + b] = d1;
}

// ---------------- 1) edge pass: ELL fill + degree; + task MLP ----------------
__global__ void __launch_bounds__(256) k_edge(
        const void* __restrict__ ei, const float* __restrict__ tf,
        const float* __restrict__ Wt1, const float* __restrict__ bt1,
        const float* __restrict__ Wt2, const float* __restrict__ bt2,
        const float* __restrict__ Wc1, const float* __restrict__ bc1) {
    int bx = blockIdx.x;
    if (bx >= 625) {
        int b = (bx - 625) * 8 + (threadIdx.x >> 5);
        do_task(b, threadIdx.x & 31, tf, Wt1, bt1, Wt2, bt2, Wc1, bc1);
        return;
    }
    int e = bx * 256 + threadIdx.x;
    int i32 = block_detect_i32((const unsigned*)ei, bx * 256);
    int s, d;
    if (i32) { const int* p = (const int*)ei; s = p[e]; d = p[NE + e]; }
    else     { const long long* p = (const long long*)ei; s = (int)p[e]; d = (int)p[NE + e]; }
    int slot = atomicAdd(&g_cnt[d], 1);
    if (slot < CAP) g_ell[d * CAP + slot] = s;
}

// ---------------- 2) layer-1: warp per node, ELL gather of x, fused matvec ----------------
__global__ void __launch_bounds__(256) k_node1(
        const float* __restrict__ x,
        const float* __restrict__ Wl1, const float* __restrict__ bl1,
        const float* __restrict__ Wr1) {
    int n    = blockIdx.x * 8 + (threadIdx.x >> 5);
    int lane = threadIdx.x & 31;
    int deg  = min(g_cnt[n], CAP);
    const int* row = g_ell + n * CAP;
    float4 a = make_float4(0.f, 0.f, 0.f, 0.f);
    for (int e = lane; e < deg; e += 32) {
        float4 xv = __ldg((const float4*)(x + (size_t)row[e] * 4));
        a.x += xv.x; a.y += xv.y; a.z += xv.z; a.w += xv.w;
    }
#pragma unroll
    for (int off = 16; off; off >>= 1) {
        a.x += __shfl_xor_sync(0xffffffffu, a.x, off);
        a.y += __shfl_xor_sync(0xffffffffu, a.y, off);
        a.z += __shfl_xor_sync(0xffffffffu, a.z, off);
        a.w += __shfl_xor_sync(0xffffffffu, a.w, off);
    }
    float invd = 1.f / fmaxf((float)deg, 1.f);
    float m0 = a.x*invd, m1 = a.y*invd, m2 = a.z*invd, m3 = a.w*invd;
    float4 xn = __ldg((const float4*)(x + (size_t)n * 4));
    int oa = 2 * lane, ob = 2 * lane + 1;
    float va = bl1[oa]
             + Wl1[oa*4]*m0 + Wl1[oa*4+1]*m1 + Wl1[oa*4+2]*m2 + Wl1[oa*4+3]*m3
             + Wr1[oa*4]*xn.x + Wr1[oa*4+1]*xn.y + Wr1[oa*4+2]*xn.z + Wr1[oa*4+3]*xn.w;
    float vb = bl1[ob]
             + Wl1[ob*4]*m0 + Wl1[ob*4+1]*m1 + Wl1[ob*4+2]*m2 + Wl1[ob*4+3]*m3
             + Wr1[ob*4]*xn.x + Wr1[ob*4+1]*xn.y + Wr1[ob*4+2]*xn.z + Wr1[ob*4+3]*xn.w;
    va = fmaxf(va, 0.f); vb = fmaxf(vb, 0.f);
    *(float2*)(g_h1 + (size_t)n * 64 + oa) = make_float2(va, vb);
    g_h1h[n * 32 + lane] = __floats2half2_rn(va, vb);
}

// ---------------- 3) mean gather over fp16 h1: warp per node, int4 edges, 4 chains ----------------
__global__ void __launch_bounds__(256) k_gather2() {
    int n    = blockIdx.x * 8 + (threadIdx.x >> 5);
    int lane = threadIdx.x & 31;
    int deg  = min(g_cnt[n], CAP);
    const int4* row = (const int4*)(g_ell + n * CAP);
    float2 a = make_float2(0.f, 0.f), b = make_float2(0.f, 0.f);
    float2 c = make_float2(0.f, 0.f), d = make_float2(0.f, 0.f);
    int nq = deg >> 2;
    for (int q = 0; q < nq; q++) {
        int4 s4 = row[q];
        float2 va = __half22float2(__ldg(&g_h1h[s4.x * 32 + lane]));
        float2 vb = __half22float2(__ldg(&g_h1h[s4.y * 32 + lane]));
        float2 vc = __half22float2(__ldg(&g_h1h[s4.z * 32 + lane]));
        float2 vd = __half22float2(__ldg(&g_h1h[s4.w * 32 + lane]));
        a.x += va.x; a.y += va.y;
        b.x += vb.x; b.y += vb.y;
        c.x += vc.x; c.y += vc.y;
        d.x += vd.x; d.y += vd.y;
    }
    for (int e = nq * 4; e < deg; e++) {
        int s = g_ell[n * CAP + e];
        float2 v = __half22float2(__ldg(&g_h1h[s * 32 + lane]));
        a.x += v.x; a.y += v.y;
    }
    float invd = 1.f / fmaxf((float)deg, 1.f);
    float2 m;
    m.x = (a.x + b.x + c.x + d.x) * invd;
    m.y = (a.y + b.y + c.y + d.y) * invd;
    *(float2*)(g_mean + (size_t)n * 64 + 2 * lane) = m;
}

// ---------------- 4) GEMM with register tile 4 outs x 2 nodes (R12-best config) ----------------
#define MM_NODES 16
#define MM_GRID  ((NN + MM_NODES - 1) / MM_NODES)    // 313
#define WS3 68
#define MS3 34
#define SM_BYTES ((3*64*WS3 + 2*64*MS3) * 4)         // 69632 B
__global__ void __launch_bounds__(128) k_l2mm(const float* __restrict__ Wl2,
                                              const float* __restrict__ bl2,
                                              const float* __restrict__ Wr2,
                                              const float* __restrict__ Wc1) {
    extern __shared__ float sm[];
    float* sWl   = sm;                   // [k*WS3 + o]
    float* sWr   = sm + 64*WS3;
    float* sWc   = sm + 2*64*WS3;
    float* sMean = sm + 3*64*WS3;        // [k*MS3 + nl]; aliased as sH2 later
    float* sX    = sMean + 64*MS3;
    int tid = threadIdx.x;
    int n0 = blockIdx.x * MM_NODES;

    for (int idx = tid; idx < 4096; idx += 128) {
        int o = idx >> 6, k = idx & 63;
        sWl[k*WS3 + o] = Wl2[idx];
        sWr[k*WS3 + o] = Wr2[idx];
        sWc[k*WS3 + o] = Wc1[o*128 + k];
    }
    for (int idx = tid; idx < 1024; idx += 128) {
        int nl = idx >> 6, k = idx & 63;
        int n = n0 + nl;
        bool ok = (n < NN);
        sMean[k*MS3 + nl] = ok ? g_mean[n*64 + k] : 0.f;
        sX[k*MS3 + nl]    = ok ? g_h1[n*64 + k]   : 0.f;
    }
    __syncthreads();

    int tx = tid & 15, ny = tid >> 4;
    int o0 = tx * 4, nl0 = ny * 2;

    float4 bb = *(const float4*)(bl2 + o0);
    float4 accA = bb, accB = bb;
#pragma unroll
    for (int k = 0; k < 64; k++) {
        float2 m  = *(const float2*)(sMean + k*MS3 + nl0);
        float2 xv = *(const float2*)(sX + k*MS3 + nl0);
        float4 wl = *(const float4*)(sWl + k*WS3 + o0);
        float4 wr = *(const float4*)(sWr + k*WS3 + o0);
        accA.x += m.x*wl.x + xv.x*wr.x; accA.y += m.x*wl.y + xv.x*wr.y;
        accA.z += m.x*wl.z + xv.x*wr.z; accA.w += m.x*wl.w + xv.x*wr.w;
        accB.x += m.y*wl.x + xv.y*wr.x; accB.y += m.y*wl.y + xv.y*wr.y;
        accB.z += m.y*wl.z + xv.y*wr.z; accB.w += m.y*wl.w + xv.y*wr.w;
    }
    accA.x = fmaxf(accA.x, 0.f); accA.y = fmaxf(accA.y, 0.f);
    accA.z = fmaxf(accA.z, 0.f); accA.w = fmaxf(accA.w, 0.f);
    accB.x = fmaxf(accB.x, 0.f); accB.y = fmaxf(accB.y, 0.f);
    accB.z = fmaxf(accB.z, 0.f); accB.w = fmaxf(accB.w, 0.f);
    __syncthreads();

    float* sH2 = sMean;
    sH2[(o0+0)*MS3 + nl0]   = accA.x; sH2[(o0+1)*MS3 + nl0]   = accA.y;
    sH2[(o0+2)*MS3 + nl0]   = accA.z; sH2[(o0+3)*MS3 + nl0]   = accA.w;
    sH2[(o0+0)*MS3 + nl0+1] = accB.x; sH2[(o0+1)*MS3 + nl0+1] = accB.y;
    sH2[(o0+2)*MS3 + nl0+1] = accB.z; sH2[(o0+3)*MS3 + nl0+1] = accB.w;
    __syncthreads();

    float4 pA = make_float4(0.f,0.f,0.f,0.f), pB = make_float4(0.f,0.f,0.f,0.f);
#pragma unroll
    for (int k = 0; k < 64; k++) {
        float2 h2 = *(const float2*)(sH2 + k*MS3 + nl0);
        float4 wc = *(const float4*)(sWc + k*WS3 + o0);
        pA.x += h2.x*wc.x; pA.y += h2.x*wc.y; pA.z += h2.x*wc.z; pA.w += h2.x*wc.w;
        pB.x += h2.y*wc.x; pB.y += h2.y*wc.y; pB.z += h2.y*wc.z; pB.w += h2.y*wc.w;
    }
    int n = n0 + nl0;
    if (n < NN)     *(float4*)(g_hp + (size_t)n * 64 + o0)       = pA;
    if (n + 1 < NN) *(float4*)(g_hp + (size_t)(n + 1) * 64 + o0) = pB;
}

// ---------------- 5) final scores: 256 nodes x 32 batches, 4 nodes/thread ----------------
// grid (20,16), 256 threads. Per h: 4 hp-LDS + 4 tp-broadcast + 1 w2 per 64 madds.
#define FIN_SMEM (64*257*4 + 64*32*4 + 64*8)     // 74496 B
__global__ void __launch_bounds__(256) k_final(const float* __restrict__ Wc2,
                                               const float* __restrict__ bc2,
                                               float* __restrict__ out) {
    extern __shared__ float smf[];
    float* s_hp = smf;                         // [h][r], stride 257 (conflict-free)
    float* s_tp = smf + 64 * 257;              // [h][b], 32 wide
    unsigned long long* s_w2 = (unsigned long long*)(smf + 64 * 257 + 64 * 32);
    int tid = threadIdx.x;

    // side job: re-zero degree counters (blocks 0..19 x 256 = 5120 >= 5000)
    int bid = blockIdx.y * gridDim.x + blockIdx.x;
    if (bid < 20) {
        int i = bid * 256 + tid;
        if (i < NN) g_cnt[i] = 0;
    }

    int n0 = blockIdx.x * 256, b0 = blockIdx.y * 32;
    for (int idx = tid; idx < 256 * 64; idx += 256) {
        int r = idx >> 6, h = idx & 63;                  // coalesced global, conflict-free smem
        s_hp[h*257 + r] = g_hp[(size_t)(n0 + r) * 64 + h];
    }
    for (int idx = tid; idx < 2048; idx += 256) {
        int h = idx >> 5, b = idx & 31;                  // g_tpT is [h][b]: coalesced
        s_tp[h*32 + b] = g_tpT[h * BATCH + b0 + b];
    }
    if (tid < 64) { float w = Wc2[tid]; s_w2[tid] = pack2(w, w); }
    __syncthreads();

    int nla = tid & 63, q = tid >> 6;          // q in {0..3}: 8 batches each
    U64 acc[4][4];                             // [node j][batch pair p]
#pragma unroll
    for (int j = 0; j < 4; j++)
#pragma unroll
        for (int p = 0; p < 4; p++) acc[j][p].u = 0ull;

#pragma unroll 2
    for (int h = 0; h < 64; h++) {
        unsigned long long ha[4];
#pragma unroll
        for (int j = 0; j < 4; j++) {
            float hv = s_hp[h*257 + nla + 64*j];
            ha[j] = pack2(hv, hv);
        }
        unsigned long long w2 = s_w2[h];
        const unsigned long long* tp = (const unsigned long long*)(s_tp + h*32 + q*8);
#pragma unroll
        for (int p = 0; p < 4; p++) {
            unsigned long long t2 = tp[p];
#pragma unroll
            for (int j = 0; j < 4; j++) {
                U64 a;
                asm("add.rn.f32x2 %0, %1, %2;" : "=l"(a.u) : "l"(t2), "l"(ha[j]));
                a.f.x = fmaxf(a.f.x, 0.f); a.f.y = fmaxf(a.f.y, 0.f);
                asm("fma.rn.f32x2 %0, %1, %2, %0;" : "+l"(acc[j][p].u) : "l"(a.u), "l"(w2));
            }
        }
    }

    float bias = bc2[0];
#pragma unroll
    for (int j = 0; j < 4; j++) {
        int n = n0 + nla + 64*j;
        if (n < NN) {
#pragma unroll
            for (int p = 0; p < 4; p++) {
                int b = b0 + q*8 + 2*p;
                out[(size_t)b       * NN + n] = acc[j][p].f.x + bias;
                out[(size_t)(b + 1) * NN + n] = acc[j][p].f.y + bias;
            }
        }
    }
}

// ---------------- launch ----------------
extern "C" void kernel_launch(void* const* d_in, const int* in_sizes, int n_in,
                              void* d_out, int out_size) {
    const float* x   = (const float*)d_in[0];
    const void*  ei  = d_in[1];
    const float* tf  = (const float*)d_in[2];
    const float* Wl1 = (const float*)d_in[3];
    const float* bl1 = (const float*)d_in[4];
    const float* Wr1 = (const float*)d_in[5];
    const float* Wl2 = (const float*)d_in[6];
    const float* bl2 = (const float*)d_in[7];
    const float* Wr2 = (const float*)d_in[8];
    const float* Wt1 = (const float*)d_in[9];
    const float* bt1 = (const float*)d_in[10];
    const float* Wt2 = (const float*)d_in[11];
    const float* bt2 = (const float*)d_in[12];
    const float* Wc1 = (const float*)d_in[13];
    const float* bc1 = (const float*)d_in[14];
    const float* Wc2 = (const float*)d_in[15];
    const float* bc2 = (const float*)d_in[16];
    float* out = (float*)d_out;

    static bool attr_set = false;
    if (!attr_set) {
        cudaFuncSetAttribute(k_l2mm,  cudaFuncAttributeMaxDynamicSharedMemorySize, SM_BYTES);
        cudaFuncSetAttribute(k_final, cudaFuncAttributeMaxDynamicSharedMemorySize, FIN_SMEM);
        attr_set = true;
    }

    k_edge   <<<689, 256>>>(ei, tf, Wt1, bt1, Wt2, bt2, Wc1, bc1);
    k_node1  <<<625, 256>>>(x, Wl1, bl1, Wr1);
    k_gather2<<<625, 256>>>();
    k_l2mm   <<<MM_GRID, 128, SM_BYTES>>>(Wl2, bl2, Wr2, Wc1);
    k_final  <<<dim3(20, 16), 256, FIN_SMEM>>>(Wc2, bc2, out);
}

// round 16
// speedup vs baseline: 1.1098x; 1.0522x over previous
#include <cuda_runtime.h>
#include <cuda_fp16.h>

#define NN     5000
#define NE     160000
#define HID    64
#define BATCH  512
#define CAP    128            // ELL row capacity (Poisson(32); P(deg>128) ~ 1e-40)

// ---------------- scratch (device globals; zero-init at module load) ----------------
__device__ int      g_cnt[NN];              // degree / ELL slot counter; re-zeroed by k_final
__device__ __align__(16) int g_ell[NN * CAP];
__device__ __align__(16) float   g_h1 [NN * HID];    // fp32 h1
__device__ __align__(8)  __half2 g_h1h[NN * 32];     // fp16 mirror (gather traffic)
__device__ __align__(16) float g_hp[5120 * HID];     // rows [5000,5120) stay zero forever
__device__ __align__(16) float g_tpT[HID * BATCH];   // transposed: [h][b]
__device__ __align__(8) __half2 g_Wl2h[64 * 32];     // [k][opair]: (Wl2[2l][k], Wl2[2l+1][k])
__device__ __align__(8) __half2 g_Wr2h[64 * 32];
__device__ __align__(8) __half2 g_Wch [64 * 32];     // Wc1 h-part

union U64 { unsigned long long u; float2 f; };

__device__ __forceinline__ unsigned long long pack2(float a, float b) {
    unsigned long long r;
    asm("mov.b64 %0, {%1, %2};" : "=l"(r) : "f"(a), "f"(b));
    return r;
}

// per-block edge dtype detection: OR of 256 odd u32 words of this block's slice.
__device__ __forceinline__ int block_detect_i32(const unsigned* __restrict__ w, int e0) {
    __shared__ unsigned s_or[8];
    __shared__ int s_i32;
    int tid = threadIdx.x;
    unsigned odd = w[2 * (e0 + tid) + 1];
    odd = __reduce_or_sync(0xffffffffu, odd);
    if ((tid & 31) == 0) s_or[tid >> 5] = odd;
    __syncthreads();
    if (tid == 0) {
        unsigned a = 0;
#pragma unroll
        for (int i = 0; i < 8; i++) a |= s_or[i];
        s_i32 = (a != 0);
    }
    __syncthreads();
    return s_i32;
}

// -------- task MLP, one warp per batch, shuffle-based --------
__device__ __forceinline__ void do_task(int b, int lane, const float* __restrict__ tf,
                                        const float* __restrict__ Wt1, const float* __restrict__ bt1,
                                        const float* __restrict__ Wt2, const float* __restrict__ bt2,
                                        const float* __restrict__ Wc1, const float* __restrict__ bc1) {
    float4 f = *(const float4*)(tf + (size_t)b * 4);
    int o0 = lane, o1 = lane + 32;
    float a0 = bt1[o0] + Wt1[o0*4]*f.x + Wt1[o0*4+1]*f.y + Wt1[o0*4+2]*f.z + Wt1[o0*4+3]*f.w;
    float a1 = bt1[o1] + Wt1[o1*4]*f.x + Wt1[o1*4+1]*f.y + Wt1[o1*4+2]*f.z + Wt1[o1*4+3]*f.w;
    a0 = fmaxf(a0, 0.f); a1 = fmaxf(a1, 0.f);

    float c0 = bt2[o0], c1 = bt2[o1];
#pragma unroll
    for (int h = 0; h < 32; h++) {
        float v = __shfl_sync(0xffffffffu, a0, h);
        c0 += Wt2[o0*64 + h] * v;
        c1 += Wt2[o1*64 + h] * v;
    }
#pragma unroll
    for (int h = 0; h < 32; h++) {
        float v = __shfl_sync(0xffffffffu, a1, h);
        c0 += Wt2[o0*64 + 32 + h] * v;
        c1 += Wt2[o1*64 + 32 + h] * v;
    }
    float d0 = bc1[o0], d1 = bc1[o1];
#pragma unroll
    for (int h = 0; h < 32; h++) {
        float v = __shfl_sync(0xffffffffu, c0, h);
        d0 += Wc1[o0*128 + 64 + h] * v;
        d1 += Wc1[o1*128 + 64 + h] * v;
    }
#pragma unroll
    for (int h = 0; h < 32; h++) {
        float v = __shfl_sync(0xffffffffu, c1, h);
        d0 += Wc1[o0*128 + 96 + h] * v;
        d1 += Wc1[o1*128 + 96 + h] * v;
    }
    g_tpT[o0 * BATCH + b] = d0;
    g_tpT[o1 * BATCH + b] = d1;
}

// ---------------- 1) edge pass: ELL fill + degree; + task MLP; + fp16 weight convert ----------------
__global__ void __launch_bounds__(256) k_edge(
        const void* __restrict__ ei, const float* __restrict__ tf,
        const float* __restrict__ Wt1, const float* __restrict__ bt1,
        const float* __restrict__ Wt2, const float* __restrict__ bt2,
        const float* __restrict__ Wc1, const float* __restrict__ bc1,
        const float* __restrict__ Wl2, const float* __restrict__ Wr2) {
    int bx = blockIdx.x;
    if (bx >= 689) {
        // fp16 weight conversion: 24 blocks x 256 = 6144 = 3 x 2048 half2 elements
        int idx = (bx - 689) * 256 + threadIdx.x;
        int arr = idx >> 11, e = idx & 2047;
        int k = e >> 5, l = e & 31;
        if (arr == 0)
            g_Wl2h[e] = __floats2half2_rn(Wl2[(2*l)*64 + k],   Wl2[(2*l+1)*64 + k]);
        else if (arr == 1)
            g_Wr2h[e] = __floats2half2_rn(Wr2[(2*l)*64 + k],   Wr2[(2*l+1)*64 + k]);
        else
            g_Wch[e]  = __floats2half2_rn(Wc1[(2*l)*128 + k],  Wc1[(2*l+1)*128 + k]);
        return;
    }
    if (bx >= 625) {
        int b = (bx - 625) * 8 + (threadIdx.x >> 5);
        do_task(b, threadIdx.x & 31, tf, Wt1, bt1, Wt2, bt2, Wc1, bc1);
        return;
    }
    int e = bx * 256 + threadIdx.x;
    int i32 = block_detect_i32((const unsigned*)ei, bx * 256);
    int s, d;
    if (i32) { const int* p = (const int*)ei; s = p[e]; d = p[NE + e]; }
    else     { const long long* p = (const long long*)ei; s = (int)p[e]; d = (int)p[NE + e]; }
    int slot = atomicAdd(&g_cnt[d], 1);
    if (slot < CAP) g_ell[d * CAP + slot] = s;
}

// ---------------- 2) layer-1: warp per node, ELL gather of x, fused matvec ----------------
__global__ void __launch_bounds__(256) k_node1(
        const float* __restrict__ x,
        const float* __restrict__ Wl1, const float* __restrict__ bl1,
        const float* __restrict__ Wr1) {
    int n    = blockIdx.x * 8 + (threadIdx.x >> 5);
    int lane = threadIdx.x & 31;
    int deg  = min(g_cnt[n], CAP);
    const int* row = g_ell + n * CAP;
    float4 a = make_float4(0.f, 0.f, 0.f, 0.f);
    for (int e = lane; e < deg; e += 32) {
        float4 xv = __ldg((const float4*)(x + (size_t)row[e] * 4));
        a.x += xv.x; a.y += xv.y; a.z += xv.z; a.w += xv.w;
    }
#pragma unroll
    for (int off = 16; off; off >>= 1) {
        a.x += __shfl_xor_sync(0xffffffffu, a.x, off);
        a.y += __shfl_xor_sync(0xffffffffu, a.y, off);
        a.z += __shfl_xor_sync(0xffffffffu, a.z, off);
        a.w += __shfl_xor_sync(0xffffffffu, a.w, off);
    }
    float invd = 1.f / fmaxf((float)deg, 1.f);
    float m0 = a.x*invd, m1 = a.y*invd, m2 = a.z*invd, m3 = a.w*invd;
    float4 xn = __ldg((const float4*)(x + (size_t)n * 4));
    int oa = 2 * lane, ob = 2 * lane + 1;
    float va = bl1[oa]
             + Wl1[oa*4]*m0 + Wl1[oa*4+1]*m1 + Wl1[oa*4+2]*m2 + Wl1[oa*4+3]*m3
             + Wr1[oa*4]*xn.x + Wr1[oa*4+1]*xn.y + Wr1[oa*4+2]*xn.z + Wr1[oa*4+3]*xn.w;
    float vb = bl1[ob]
             + Wl1[ob*4]*m0 + Wl1[ob*4+1]*m1 + Wl1[ob*4+2]*m2 + Wl1[ob*4+3]*m3
             + Wr1[ob*4]*xn.x + Wr1[ob*4+1]*xn.y + Wr1[ob*4+2]*xn.z + Wr1[ob*4+3]*xn.w;
    va = fmaxf(va, 0.f); vb = fmaxf(vb, 0.f);
    *(float2*)(g_h1 + (size_t)n * 64 + oa) = make_float2(va, vb);
    g_h1h[n * 32 + lane] = __floats2half2_rn(va, vb);
}

// ---------------- 3) FUSED gather + layer-2 + projection (warp per node) ----------------
// grid 625 x 256: 8 warps = 8 nodes per block. smem ~29KB -> 7 blocks/SM.
// Phase A: stage fp16 weights (one sync). Phase B: warp gathers mean (registers->smem col).
// Phase C: per-lane 2-out GEMM reading own-warp smem columns (broadcast) + fp16 weights.
#define FS 9   // feature smem stride
__global__ void __launch_bounds__(256) k_l2f(const float* __restrict__ bl2) {
    __shared__ __half2 sWl[64 * 32], sWr[64 * 32], sWc[64 * 32];
    __shared__ float sMean[64 * FS], sX[64 * FS];    // [k*FS + nodelocal]
    int tid  = threadIdx.x;
    int w    = tid >> 5;          // node-local 0..7
    int lane = tid & 31;
    int n    = blockIdx.x * 8 + w;

    // Phase A: stage weights (uint32 copies)
    {
        const unsigned* srcL = (const unsigned*)g_Wl2h;
        const unsigned* srcR = (const unsigned*)g_Wr2h;
        const unsigned* srcC = (const unsigned*)g_Wch;
        unsigned* dstL = (unsigned*)sWl;
        unsigned* dstR = (unsigned*)sWr;
        unsigned* dstC = (unsigned*)sWc;
        for (int i = tid; i < 2048; i += 256) {
            dstL[i] = srcL[i];
            dstR[i] = srcR[i];
            dstC[i] = srcC[i];
        }
    }

    // Phase B: gather mean over fp16 h1 (4 chains, int4 edge loads)
    {
        int deg = min(g_cnt[n], CAP);
        const int4* row = (const int4*)(g_ell + n * CAP);
        float2 a = make_float2(0.f, 0.f), b = make_float2(0.f, 0.f);
        float2 c = make_float2(0.f, 0.f), d = make_float2(0.f, 0.f);
        int nq = deg >> 2;
        for (int q = 0; q < nq; q++) {
            int4 s4 = row[q];
            float2 va = __half22float2(__ldg(&g_h1h[s4.x * 32 + lane]));
            float2 vb = __half22float2(__ldg(&g_h1h[s4.y * 32 + lane]));
            float2 vc = __half22float2(__ldg(&g_h1h[s4.z * 32 + lane]));
            float2 vd = __half22float2(__ldg(&g_h1h[s4.w * 32 + lane]));
            a.x += va.x; a.y += va.y;
            b.x += vb.x; b.y += vb.y;
            c.x += vc.x; c.y += vc.y;
            d.x += vd.x; d.y += vd.y;
        }
        for (int e = nq * 4; e < deg; e++) {
            int s = g_ell[n * CAP + e];
            float2 v = __half22float2(__ldg(&g_h1h[s * 32 + lane]));
            a.x += v.x; a.y += v.y;
        }
        float invd = 1.f / fmaxf((float)deg, 1.f);
        float mx = (a.x + b.x + c.x + d.x) * invd;
        float my = (a.y + b.y + c.y + d.y) * invd;
        float2 xd = *(const float2*)(g_h1 + (size_t)n * 64 + 2 * lane);
        sMean[(2*lane)  *FS + w] = mx;
        sMean[(2*lane+1)*FS + w] = my;
        sX[(2*lane)  *FS + w] = xd.x;
        sX[(2*lane+1)*FS + w] = xd.y;
    }
    __syncthreads();   // weights staged by all warps; features are warp-local but sync anyway

    // Phase C1: h2 = relu(Wl2@mean + bl2 + Wr2@x), lane owns outs 2lane,2lane+1
    int o0 = 2 * lane;
    float2 acc = *(const float2*)(bl2 + o0);
#pragma unroll
    for (int k = 0; k < 64; k++) {
        float m  = sMean[k*FS + w];                     // broadcast within warp
        float xv = sX[k*FS + w];
        float2 wl = __half22float2(sWl[k*32 + lane]);
        float2 wr = __half22float2(sWr[k*32 + lane]);
        acc.x += m*wl.x + xv*wr.x;
        acc.y += m*wl.y + xv*wr.y;
    }
    float2 h2 = make_float2(fmaxf(acc.x, 0.f), fmaxf(acc.y, 0.f));

    // write h2 into own-warp columns (reuse sMean), warp-local sync
    __syncwarp();
    sMean[(o0)  *FS + w] = h2.x;
    sMean[(o0+1)*FS + w] = h2.y;
    __syncwarp();

    // Phase C2: hp = h2 @ Wc1h^T
    float2 p = make_float2(0.f, 0.f);
#pragma unroll
    for (int k = 0; k < 64; k++) {
        float hv = sMean[k*FS + w];
        float2 wc = __half22float2(sWc[k*32 + lane]);
        p.x += hv*wc.x;
        p.y += hv*wc.y;
    }
    *(float2*)(g_hp + (size_t)n * 64 + o0) = p;
}

// ---------------- 4) final scores + re-zero side job (R12-best config) ----------------
// Tile 128 nodes x 64 batches, 256 threads, grid (40,8).
#define FIN_SMEM (64*129*4 + 64*64*4 + 64*8)
__global__ void __launch_bounds__(256) k_final(const float* __restrict__ Wc2,
                                               const float* __restrict__ bc2,
                                               float* __restrict__ out) {
    extern __shared__ float smf[];
    float* s_hp = smf;                         // [h][r], stride 129
    float* s_tp = smf + 64 * 129;              // [h][b], 64 wide
    unsigned long long* s_w2 = (unsigned long long*)(smf + 64 * 129 + 64 * 64);
    int tid = threadIdx.x;

    // side job: re-zero degree counters
    int bid = blockIdx.y * gridDim.x + blockIdx.x;
    if (bid < 20) {
        int i = bid * 256 + tid;
        if (i < NN) g_cnt[i] = 0;
    }

    int n0 = blockIdx.x * 128, b0 = blockIdx.y * 64;
    for (int idx = tid; idx < 8192; idx += 256) {
        int r = idx >> 6, h = idx & 63;
        s_hp[h*129 + r] = g_hp[(size_t)(n0 + r) * 64 + h];
    }
    for (int idx = tid; idx < 4096; idx += 256) {
        int h = idx >> 6, b = idx & 63;
        s_tp[h*64 + b] = g_tpT[h * BATCH + b0 + b];
    }
    if (tid < 64) { float w = Wc2[tid]; s_w2[tid] = pack2(w, w); }
    __syncthreads();

    int nla = tid & 63, q = tid >> 6;          // q in {0..3}: 16 batches each
    int nlb = nla + 64;
    U64 accA[8], accB[8];
#pragma unroll
    for (int p = 0; p < 8; p++) { accA[p].u = 0ull; accB[p].u = 0ull; }

#pragma unroll 4
    for (int h = 0; h < 64; h++) {
        float hva = s_hp[h*129 + nla];
        float hvb = s_hp[h*129 + nlb];
        unsigned long long ha = pack2(hva, hva);
        unsigned long long hb = pack2(hvb, hvb);
        unsigned long long w2 = s_w2[h];
        const unsigned long long* tp = (const unsigned long long*)(s_tp + h*64 + q*16);
#pragma unroll
        for (int p = 0; p < 8; p++) {
            unsigned long long t2 = tp[p];
            U64 a, b;
            asm("add.rn.f32x2 %0, %1, %2;" : "=l"(a.u) : "l"(t2), "l"(ha));
            asm("add.rn.f32x2 %0, %1, %2;" : "=l"(b.u) : "l"(t2), "l"(hb));
            a.f.x = fmaxf(a.f.x, 0.f); a.f.y = fmaxf(a.f.y, 0.f);
            b.f.x = fmaxf(b.f.x, 0.f); b.f.y = fmaxf(b.f.y, 0.f);
            asm("fma.rn.f32x2 %0, %1, %2, %0;" : "+l"(accA[p].u) : "l"(a.u), "l"(w2));
            asm("fma.rn.f32x2 %0, %1, %2, %0;" : "+l"(accB[p].u) : "l"(b.u), "l"(w2));
        }
    }

    float bias = bc2[0];
    int na = n0 + nla, nb = n0 + nlb;
    if (na < NN) {
#pragma unroll
        for (int p = 0; p < 8; p++) {
            int b = b0 + q*16 + 2*p;
            out[(size_t)b       * NN + na] = accA[p].f.x + bias;
            out[(size_t)(b + 1) * NN + na] = accA[p].f.y + bias;
        }
    }
    if (nb < NN) {
#pragma unroll
        for (int p = 0; p < 8; p++) {
            int b = b0 + q*16 + 2*p;
            out[(size_t)b       * NN + nb] = accB[p].f.x + bias;
            out[(size_t)(b + 1) * NN + nb] = accB[p].f.y + bias;
        }
    }
}

// ---------------- launch ----------------
extern "C" void kernel_launch(void* const* d_in, const int* in_sizes, int n_in,
                              void* d_out, int out_size) {
    const float* x   = (const float*)d_in[0];
    const void*  ei  = d_in[1];
    const float* tf  = (const float*)d_in[2];
    const float* Wl1 = (const float*)d_in[3];
    const float* bl1 = (const float*)d_in[4];
    const float* Wr1 = (const float*)d_in[5];
    const float* Wl2 = (const float*)d_in[6];
    const float* bl2 = (const float*)d_in[7];
    const float* Wr2 = (const float*)d_in[8];
    const float* Wt1 = (const float*)d_in[9];
    const float* bt1 = (const float*)d_in[10];
    const float* Wt2 = (const float*)d_in[11];
    const float* bt2 = (const float*)d_in[12];
    const float* Wc1 = (const float*)d_in[13];
    const float* bc1 = (const float*)d_in[14];
    const float* Wc2 = (const float*)d_in[15];
    const float* bc2 = (const float*)d_in[16];
    float* out = (float*)d_out;

    static bool attr_set = false;
    if (!attr_set) {
        cudaFuncSetAttribute(k_final, cudaFuncAttributeMaxDynamicSharedMemorySize, FIN_SMEM);
        attr_set = true;
    }

    k_edge  <<<713, 256>>>(ei, tf, Wt1, bt1, Wt2, bt2, Wc1, bc1, Wl2, Wr2);
    k_node1 <<<625, 256>>>(x, Wl1, bl1, Wr1);
    k_l2f   <<<625, 256>>>(bl2);
    k_final <<<dim3(40, 8), 256, FIN_SMEM>>>(Wc2, bc2, out);
}